// round 13
// baseline (speedup 1.0000x reference)
#include <cuda_runtime.h>

// Problem constants
#define BI 4
#define SS 1024
#define DM 1024
#define NH 16
#define DH 64
#define MROWS (BI * SS)            // 4096
#define OUT_ELEMS (MROWS * DM)     // 4194304
#define ATTN_ELEMS ((size_t)BI * NH * SS * SS)
#define MASK_ELEMS ((size_t)BI * SS * SS)      // 4194304

// Scratch (device globals; allocation inside kernel_launch is forbidden)
__device__ float g_xq[MROWS * DM];   // tf32-rounded Qin
__device__ float g_xk[MROWS * DM];   // tf32-rounded Kin
__device__ float g_xv[MROWS * DM];   // tf32-rounded Vin
__device__ float g_wq[DM * DM];      // tf32-rounded weights
__device__ float g_wk[DM * DM];
__device__ float g_wv[DM * DM];
__device__ float g_wo[DM * DM];
__device__ float g_q[MROWS * DM];    // projections (tf32-rounded values)
__device__ float g_k[MROWS * DM];
__device__ float g_v[MROWS * DM];
__device__ float g_ctx[MROWS * DM];  // tf32-rounded context
__device__ float g_y[MROWS * DM];    // pre-LN (fp32)
__device__ float g_attn[ATTN_ELEMS]; // only used if attn not in d_out
__device__ unsigned char g_mask8[MASK_ELEMS];  // mask as u8 (canonical form)
__device__ int   g_mask_is_int32;

// ---------------------------------------------------------------------------
// tf32 + cp.async helpers
// ---------------------------------------------------------------------------
__device__ __forceinline__ float f2tf(float x) {
    unsigned u;
    asm("cvt.rna.tf32.f32 %0, %1;" : "=r"(u) : "f"(x));
    return __uint_as_float(u);
}
__device__ __forceinline__ float4 tf32x4(float4 v) {
    return make_float4(f2tf(v.x), f2tf(v.y), f2tf(v.z), f2tf(v.w));
}
__device__ __forceinline__ void cpa16(const void* smem_dst, const void* gmem_src) {
    unsigned d = (unsigned)__cvta_generic_to_shared(smem_dst);
    asm volatile("cp.async.ca.shared.global [%0], [%1], 16;" :: "r"(d), "l"(gmem_src));
}
#define CPC    asm volatile("cp.async.commit_group;")
#define CPW(n) asm volatile("cp.async.wait_group %0;" :: "n"(n))

#define MMA_TF32(d, a, b0, b1) \
    asm volatile("mma.sync.aligned.m16n8k8.row.col.f32.tf32.tf32.f32 " \
                 "{%0,%1,%2,%3}, {%4,%5,%6,%7}, {%8,%9}, {%0,%1,%2,%3};" \
                 : "+f"(d[0]), "+f"(d[1]), "+f"(d[2]), "+f"(d[3]) \
                 : "r"(a[0]), "r"(a[1]), "r"(a[2]), "r"(a[3]), "r"(b0), "r"(b1))

// ---------------------------------------------------------------------------
// Mask dtype detection + canonicalize to u8.
// ---------------------------------------------------------------------------
__global__ void detect_mask_kernel(const unsigned* m) {
    int ok = 1;
    for (int i = threadIdx.x; i < 1024; i += 32)
        if (m[i] > 1u) ok = 0;
    unsigned b = __ballot_sync(0xffffffffu, ok);
    if (threadIdx.x == 0) g_mask_is_int32 = (b == 0xffffffffu) ? 1 : 0;
}
__global__ void mask_to_u8_kernel(const void* __restrict__ mask) {
    size_t i = (size_t)blockIdx.x * blockDim.x + threadIdx.x;  // uchar4 id
    uchar4 o;
    if (g_mask_is_int32) {
        int4 v = ((const int4*)mask)[i];
        o = make_uchar4(v.x != 0, v.y != 0, v.z != 0, v.w != 0);
    } else {
        o = ((const uchar4*)mask)[i];
    }
    ((uchar4*)g_mask8)[i] = o;
}

// ---------------------------------------------------------------------------
// Pre-round operands to tf32 once.
// ---------------------------------------------------------------------------
__global__ void round_inputs_kernel(const float* __restrict__ Q,
                                    const float* __restrict__ K,
                                    const float* __restrict__ V) {
    const float* s = blockIdx.z == 0 ? Q : blockIdx.z == 1 ? K : V;
    float* d = blockIdx.z == 0 ? g_xq : blockIdx.z == 1 ? g_xk : g_xv;
    size_t i = (size_t)blockIdx.x * blockDim.x + threadIdx.x;
    ((float4*)d)[i] = tf32x4(((const float4*)s)[i]);
}
__global__ void round_weights_kernel(const float* __restrict__ Wq,
                                     const float* __restrict__ Wk,
                                     const float* __restrict__ Wv,
                                     const float* __restrict__ Wo) {
    const float* s = blockIdx.z == 0 ? Wq : blockIdx.z == 1 ? Wk :
                     blockIdx.z == 2 ? Wv : Wo;
    float* d = blockIdx.z == 0 ? g_wq : blockIdx.z == 1 ? g_wk :
               blockIdx.z == 2 ? g_wv : g_wo;
    size_t i = (size_t)blockIdx.x * blockDim.x + threadIdx.x;
    ((float4*)d)[i] = tf32x4(((const float4*)s)[i]);
}

// ---------------------------------------------------------------------------
// 3-stage cp.async pipelined tf32 GEMM body (operands pre-rounded to tf32).
// KC = 16-wide sub-chunks per stage (stage covers K-slab of 16*KC; ONE
// __syncthreads per stage). NT threads, warps MW x (NT/32/MW);
// warp tile (MF*16) x (NF*8).
// A smem: KC sub-blocks of [BM][20] — frag banks (20r + cq) % 32 distinct.
// B smem: [16*KC][BNS], BNS % 32 == 8 — frag banks (8cq + r) % 32 distinct.
// ---------------------------------------------------------------------------
template<int NT, int MW, int MF, int NF, int BNS, int KC>
__device__ __forceinline__ void gemm_pipe(
    const float* __restrict__ A, int lda,
    const float* __restrict__ B, int ldb,
    int K, float* __restrict__ sm,
    float (&acc)[MF][NF][4])
{
    constexpr int NWARP = NT / 32;
    constexpr int BM = MW * MF * 16;
    constexpr int BN = (NWARP / MW) * NF * 8;
    constexpr int BK = 16 * KC;
    constexpr int STG = KC * BM * 20 + BK * BNS;    // floats per stage
    constexpr int KQ = BK / 4;                       // float4 per A row
    constexpr int LA = BM * KQ / NT;
    constexpr int LB = BK * (BN / 4) / NT;
    const int tid = threadIdx.x;
    const int lane = tid & 31, wid = tid >> 5;
    const int wm = (wid & (MW - 1)) * (MF * 16);
    const int wn = (wid / MW) * (NF * 8);
    const int r = lane >> 2, cq = lane & 3;
    const int nst = K / BK;

    auto issue = [&](int c) {
        float* As = sm + (c % 3) * STG;
        float* Bs = As + KC * BM * 20;
        const int k0 = c * BK;
        #pragma unroll
        for (int i = 0; i < LA; i++) {
            int f = tid + i * NT;
            int m = f / KQ, kq = f % KQ;
            int sub = kq >> 2, k4 = (kq & 3) << 2;
            cpa16(As + sub * BM * 20 + m * 20 + k4,
                  A + (size_t)m * lda + k0 + kq * 4);
        }
        #pragma unroll
        for (int i = 0; i < LB; i++) {
            int f = tid + i * NT;
            int k = f / (BN / 4), n4 = (f % (BN / 4)) << 2;
            cpa16(Bs + k * BNS + n4, B + (size_t)(k0 + k) * ldb + n4);
        }
    };

    issue(0); CPC;
    issue(1); CPC;
    for (int c = 0; c < nst; c++) {
        if (c + 2 < nst) {
            CPW(1);
            __syncthreads();
            issue(c + 2); CPC;
        } else {
            CPW(0);
            __syncthreads();
        }
        const unsigned* As0 = (const unsigned*)(sm + (c % 3) * STG);
        const unsigned* Bs0 = As0 + KC * BM * 20;
        #pragma unroll
        for (int sub = 0; sub < KC; sub++) {
            const unsigned* As = As0 + sub * BM * 20;
            const unsigned* Bs = Bs0 + sub * 16 * BNS;
            #pragma unroll
            for (int ks = 0; ks < 2; ks++) {
                const int cc = ks * 8 + cq;
                unsigned a[MF][4];
                #pragma unroll
                for (int mf = 0; mf < MF; mf++) {
                    const unsigned* p = As + (wm + mf * 16 + r) * 20 + cc;
                    a[mf][0] = p[0];
                    a[mf][1] = p[8 * 20];
                    a[mf][2] = p[4];
                    a[mf][3] = p[8 * 20 + 4];
                }
                #pragma unroll
                for (int nf = 0; nf < NF; nf++) {
                    const int n = wn + nf * 8 + r;
                    unsigned b0 = Bs[cc * BNS + n];
                    unsigned b1 = Bs[(cc + 4) * BNS + n];
                    #pragma unroll
                    for (int mf = 0; mf < MF; mf++) {
                        MMA_TF32(acc[mf][nf], a[mf], b0, b1);
                    }
                }
            }
        }
    }
}

#define QKV_SMEM_BYTES  (3 * (2 * 128 * 20 + 32 * 136) * 4)   // 113664 (2 CTA/SM)
#define CTX_SMEM_BYTES  (3 * (256 * 20 + 16 * 72) * 4)        // 75264

// ---------------------------------------------------------------------------
// 1) Fused QKV projections (NN): M=4096, N=1024, K=1024. Grid (8, 32, 3).
//    128 threads = 4 warps of 64x64; BM=128, BN=128, K-stage=32; 2 CTAs/SM.
// ---------------------------------------------------------------------------
__global__ __launch_bounds__(128, 2) void qkv_gemm(
    const float* __restrict__ bq, const float* __restrict__ bk,
    const float* __restrict__ bv)
{
    extern __shared__ float sm[];
    const float* A; const float* W; const float* bias; float* C;
    if (blockIdx.z == 0)      { A = g_xq; W = g_wq; bias = bq; C = g_q; }
    else if (blockIdx.z == 1) { A = g_xk; W = g_wk; bias = bk; C = g_k; }
    else                      { A = g_xv; W = g_wv; bias = bv; C = g_v; }
    const int bm = blockIdx.y * 128, bn = blockIdx.x * 128;
    float acc[4][8][4] = {};
    gemm_pipe<128, 2, 4, 8, 136, 2>(A + (size_t)bm * DM, DM, W + bn, DM, DM, sm, acc);

    const int lane = threadIdx.x & 31, wid = threadIdx.x >> 5;
    const int wm = (wid & 1) * 64, wn = (wid >> 1) * 64;
    const int r = lane >> 2, cq = lane & 3;
    #pragma unroll
    for (int mf = 0; mf < 4; mf++) {
        #pragma unroll
        for (int nf = 0; nf < 8; nf++) {
            int row = bm + wm + mf * 16 + r;
            int col = bn + wn + nf * 8 + 2 * cq;
            float2 bia = *(const float2*)&bias[col];
            *(float2*)&C[(size_t)row * DM + col] =
                make_float2(f2tf(acc[mf][nf][0] + bia.x), f2tf(acc[mf][nf][1] + bia.y));
            *(float2*)&C[(size_t)(row + 8) * DM + col] =
                make_float2(f2tf(acc[mf][nf][2] + bia.x), f2tf(acc[mf][nf][3] + bia.y));
        }
    }
}

// ---------------------------------------------------------------------------
// 2) FUSED scores + mask + softmax (mask read as u8 from g_mask8).
// ---------------------------------------------------------------------------
#define FUS_STRIDE 1028
#define FUS_SMEM_BYTES ((32 * FUS_STRIDE + 32 * 68 + 2 * 128 * 68) * 4)  // 209920

__global__ __launch_bounds__(256) void scores_softmax_kernel(
    float* __restrict__ attn_ext, int use_ext)
{
    extern __shared__ float sm[];
    float* Ss = sm;                          // [32][1028]
    float* Qs = Ss + 32 * FUS_STRIDE;        // [32][68]
    float* Ks = Qs + 32 * 68;                // 2 stages x [128][68]
    const int tid = threadIdx.x, lane = tid & 31, wid = tid >> 5;
    const int r = lane >> 2, cq = lane & 3;
    const int bh = blockIdx.y, b = bh >> 4, h = bh & 15;
    const int i0 = blockIdx.x * 32;
    const float* qb = g_q + (size_t)b * SS * DM + h * DH + (size_t)i0 * DM;
    const float* kb = g_k + (size_t)b * SS * DM + h * DH;

    #pragma unroll
    for (int i = 0; i < 2; i++) {
        int f = tid + i * 256;
        int m = f >> 4, k4 = (f & 15) << 2;
        cpa16(Qs + m * 68 + k4, qb + (size_t)m * DM + k4);
    }
    auto issueK = [&](int jt) {
        float* Kst = Ks + (jt & 1) * (128 * 68);
        const float* kbj = kb + (size_t)jt * 128 * DM;
        #pragma unroll
        for (int i = 0; i < 8; i++) {
            int f = tid + i * 256;
            int m = f >> 4, k4 = (f & 15) << 2;
            cpa16(Kst + m * 68 + k4, kbj + (size_t)m * DM + k4);
        }
    };
    issueK(0); CPC;

    const int wm = (wid & 1) * 16, wn = (wid >> 1) * 32;
    for (int jt = 0; jt < 8; jt++) {
        if (jt < 7) { issueK(jt + 1); CPC; CPW(1); }
        else        { CPW(0); }
        __syncthreads();
        const unsigned* Qu = (const unsigned*)Qs;
        const unsigned* Ku = (const unsigned*)(Ks + (jt & 1) * (128 * 68));
        float acc[4][4] = {};
        #pragma unroll
        for (int kc = 0; kc < 8; kc++) {
            const int cc = kc * 8 + cq;
            unsigned a[4];
            const unsigned* pa = Qu + (wm + r) * 68 + cc;
            a[0] = pa[0]; a[1] = pa[8 * 68]; a[2] = pa[4]; a[3] = pa[8 * 68 + 4];
            #pragma unroll
            for (int nf = 0; nf < 4; nf++) {
                const unsigned* pb = Ku + (wn + nf * 8 + r) * 68 + cc;
                MMA_TF32(acc[nf], a, pb[0], pb[4]);
            }
        }
        #pragma unroll
        for (int nf = 0; nf < 4; nf++) {
            int col = jt * 128 + wn + nf * 8 + 2 * cq;
            *(float2*)&Ss[(wm + r) * FUS_STRIDE + col] =
                make_float2(acc[nf][0], acc[nf][1]);
            *(float2*)&Ss[(wm + r + 8) * FUS_STRIDE + col] =
                make_float2(acc[nf][2], acc[nf][3]);
        }
        __syncthreads();
    }

    float* attn = use_ext ? attn_ext : g_attn;
    #pragma unroll
    for (int rl = 0; rl < 4; rl++) {
        int row = wid * 4 + rl;
        size_t mbase = (size_t)b * SS * SS + (size_t)(i0 + row) * SS;
        float mx = -3.4e38f;
        #pragma unroll
        for (int it = 0; it < 8; it++) {
            int c0 = (it * 32 + lane) * 4;
            float4 s4 = *(float4*)&Ss[row * FUS_STRIDE + c0];
            uchar4 u = *(const uchar4*)(g_mask8 + mbase + c0);
            s4.x = u.x ? -1e9f : s4.x * 0.125f;
            s4.y = u.y ? -1e9f : s4.y * 0.125f;
            s4.z = u.z ? -1e9f : s4.z * 0.125f;
            s4.w = u.w ? -1e9f : s4.w * 0.125f;
            *(float4*)&Ss[row * FUS_STRIDE + c0] = s4;
            mx = fmaxf(mx, fmaxf(fmaxf(s4.x, s4.y), fmaxf(s4.z, s4.w)));
        }
        #pragma unroll
        for (int o = 16; o; o >>= 1) mx = fmaxf(mx, __shfl_xor_sync(0xffffffffu, mx, o));
        float M = __shfl_sync(0xffffffffu, mx, 0);

        float s = 0.f;
        #pragma unroll
        for (int it = 0; it < 8; it++) {
            int c0 = (it * 32 + lane) * 4;
            float4 v = *(float4*)&Ss[row * FUS_STRIDE + c0];
            v.x = __expf(v.x - M); v.y = __expf(v.y - M);
            v.z = __expf(v.z - M); v.w = __expf(v.w - M);
            *(float4*)&Ss[row * FUS_STRIDE + c0] = v;
            s += v.x + v.y + v.z + v.w;
        }
        #pragma unroll
        for (int o = 16; o; o >>= 1) s += __shfl_xor_sync(0xffffffffu, s, o);
        float inv = 1.0f / s;

        size_t abase = (size_t)bh * SS * SS + (size_t)(i0 + row) * SS;
        #pragma unroll
        for (int it = 0; it < 8; it++) {
            int c0 = (it * 32 + lane) * 4;
            float4 v = *(float4*)&Ss[row * FUS_STRIDE + c0];
            *(float4*)&attn[abase + c0] =
                make_float4(f2tf(v.x * inv), f2tf(v.y * inv),
                            f2tf(v.z * inv), f2tf(v.w * inv));
        }
    }
}

// ---------------------------------------------------------------------------
// 3) Context (NN): per bh M=1024, N=64, K=1024. Grid (1, 4, 64). KC=1.
// ---------------------------------------------------------------------------
__global__ __launch_bounds__(256) void context_kernel(const float* __restrict__ attn_ext, int use_ext) {
    extern __shared__ float sm[];
    const int bh = blockIdx.z, b = bh >> 4, h = bh & 15;
    const int bi = blockIdx.y * 256;
    const float* attn = use_ext ? attn_ext : g_attn;
    const float* ab = attn + (size_t)bh * SS * SS + (size_t)bi * SS;
    const float* vb = g_v + (size_t)b * SS * DM + h * DH;
    float acc[4][4][4] = {};
    gemm_pipe<256, 4, 4, 4, 72, 1>(ab, SS, vb, DM, SS, sm, acc);

    const int lane = threadIdx.x & 31, wid = threadIdx.x >> 5;
    const int wm = (wid & 3) * 64, wn = (wid >> 2) * 32;
    const int r = lane >> 2, cq = lane & 3;
    float* cb = g_ctx + (size_t)b * SS * DM + h * DH;
    #pragma unroll
    for (int mf = 0; mf < 4; mf++) {
        #pragma unroll
        for (int nf = 0; nf < 4; nf++) {
            int row = bi + wm + mf * 16 + r;
            int col = wn + nf * 8 + 2 * cq;
            *(float2*)&cb[(size_t)row * DM + col] =
                make_float2(f2tf(acc[mf][nf][0]), f2tf(acc[mf][nf][1]));
            *(float2*)&cb[(size_t)(row + 8) * DM + col] =
                make_float2(f2tf(acc[mf][nf][2]), f2tf(acc[mf][nf][3]));
        }
    }
}

// ---------------------------------------------------------------------------
// 4) Output projection + residual (NN). Grid (8, 32), 128 thr, 2 CTAs/SM.
// ---------------------------------------------------------------------------
__global__ __launch_bounds__(128, 2) void outproj_kernel(
    const float* __restrict__ bo, const float* __restrict__ Qres)
{
    extern __shared__ float sm[];
    const int bm = blockIdx.y * 128, bn = blockIdx.x * 128;
    float acc[4][8][4] = {};
    gemm_pipe<128, 2, 4, 8, 136, 2>(g_ctx + (size_t)bm * DM, DM, g_wo + bn, DM, DM, sm, acc);

    const int lane = threadIdx.x & 31, wid = threadIdx.x >> 5;
    const int wm = (wid & 1) * 64, wn = (wid >> 1) * 64;
    const int r = lane >> 2, cq = lane & 3;
    #pragma unroll
    for (int mf = 0; mf < 4; mf++) {
        #pragma unroll
        for (int nf = 0; nf < 8; nf++) {
            int row = bm + wm + mf * 16 + r;
            int col = bn + wn + nf * 8 + 2 * cq;
            float2 bia = *(const float2*)&bo[col];
            float2 q0 = *(const float2*)&Qres[(size_t)row * DM + col];
            float2 q1 = *(const float2*)&Qres[(size_t)(row + 8) * DM + col];
            *(float2*)&g_y[(size_t)row * DM + col] =
                make_float2(acc[mf][nf][0] + bia.x + q0.x, acc[mf][nf][1] + bia.y + q0.y);
            *(float2*)&g_y[(size_t)(row + 8) * DM + col] =
                make_float2(acc[mf][nf][2] + bia.x + q1.x, acc[mf][nf][3] + bia.y + q1.y);
        }
    }
}

// ---------------------------------------------------------------------------
// 5) LayerNorm over last dim (1024), biased variance, eps 1e-5. Grid 4096x256.
// ---------------------------------------------------------------------------
__global__ __launch_bounds__(256) void ln_kernel(
    const float* __restrict__ gamma, const float* __restrict__ beta,
    float* __restrict__ out)
{
    const float4* row = (const float4*)(g_y + (size_t)blockIdx.x * DM);
    const int t = threadIdx.x, lane = t & 31, w = t >> 5;
    __shared__ float s1[8], s2[8];
    float4 x = row[t];
    float a = x.x + x.y + x.z + x.w;
    float b = x.x * x.x + x.y * x.y + x.z * x.z + x.w * x.w;
    #pragma unroll
    for (int o = 16; o > 0; o >>= 1) {
        a += __shfl_xor_sync(0xffffffffu, a, o);
        b += __shfl_xor_sync(0xffffffffu, b, o);
    }
    if (lane == 0) { s1[w] = a; s2[w] = b; }
    __syncthreads();
    float A = 0.f, B2 = 0.f;
    #pragma unroll
    for (int i = 0; i < 8; i++) { A += s1[i]; B2 += s2[i]; }
    float mean = A * (1.0f / 1024.0f);
    float var = B2 * (1.0f / 1024.0f) - mean * mean;
    float rstd = rsqrtf(var + 1e-5f);
    float4 g = ((const float4*)gamma)[t];
    float4 be = ((const float4*)beta)[t];
    float4 o4;
    o4.x = (x.x - mean) * rstd * g.x + be.x;
    o4.y = (x.y - mean) * rstd * g.y + be.y;
    o4.z = (x.z - mean) * rstd * g.z + be.z;
    o4.w = (x.w - mean) * rstd * g.w + be.w;
    ((float4*)(out + (size_t)blockIdx.x * DM))[t] = o4;
}

// ---------------------------------------------------------------------------
extern "C" void kernel_launch(void* const* d_in, const int* in_sizes, int n_in,
                              void* d_out, int out_size) {
    const float* Qin   = (const float*)d_in[0];
    const void*  mask  = d_in[3];
    const float* Wq    = (const float*)d_in[4];
    const float* bq    = (const float*)d_in[5];
    const float* Wk    = (const float*)d_in[6];
    const float* bk    = (const float*)d_in[7];
    const float* Wv    = (const float*)d_in[8];
    const float* bv    = (const float*)d_in[9];
    const float* Wo    = (const float*)d_in[10];
    const float* bo    = (const float*)d_in[11];
    const float* gamma = (const float*)d_in[12];
    const float* beta  = (const float*)d_in[13];
    float* out = (float*)d_out;

    const int use_ext = (out_size > OUT_ELEMS) ? 1 : 0;
    float* attn_ext = out + OUT_ELEMS;

    cudaFuncSetAttribute(qkv_gemm, cudaFuncAttributeMaxDynamicSharedMemorySize, QKV_SMEM_BYTES);
    cudaFuncSetAttribute(outproj_kernel, cudaFuncAttributeMaxDynamicSharedMemorySize, QKV_SMEM_BYTES);
    cudaFuncSetAttribute(scores_softmax_kernel, cudaFuncAttributeMaxDynamicSharedMemorySize, FUS_SMEM_BYTES);
    cudaFuncSetAttribute(context_kernel, cudaFuncAttributeMaxDynamicSharedMemorySize, CTX_SMEM_BYTES);

    detect_mask_kernel<<<1, 32>>>((const unsigned*)mask);
    mask_to_u8_kernel<<<dim3(MASK_ELEMS / 4 / 256), 256>>>(mask);
    round_inputs_kernel<<<dim3(MROWS * DM / 4 / 256, 1, 3), 256>>>(
        Qin, (const float*)d_in[1], (const float*)d_in[2]);
    round_weights_kernel<<<dim3(DM * DM / 4 / 256, 1, 4), 256>>>(Wq, Wk, Wv, Wo);
    qkv_gemm<<<dim3(8, 32, 3), 128, QKV_SMEM_BYTES>>>(bq, bk, bv);
    scores_softmax_kernel<<<dim3(32, 64), 256, FUS_SMEM_BYTES>>>(attn_ext, use_ext);
    context_kernel<<<dim3(1, 4, 64), 256, CTX_SMEM_BYTES>>>(attn_ext, use_ext);
    outproj_kernel<<<dim3(8, 32), 128, QKV_SMEM_BYTES>>>(bo, Qin);
    ln_kernel<<<dim3(MROWS), 256>>>(gamma, beta, out);
    (void)in_sizes; (void)n_in;
}

// round 14
// speedup vs baseline: 1.0788x; 1.0788x over previous
#include <cuda_runtime.h>

// Problem constants
#define BI 4
#define SS 1024
#define DM 1024
#define NH 16
#define DH 64
#define MROWS (BI * SS)            // 4096
#define OUT_ELEMS (MROWS * DM)     // 4194304
#define ATTN_ELEMS ((size_t)BI * NH * SS * SS)
#define MASK_ELEMS ((size_t)BI * SS * SS)      // 4194304

// Scratch (device globals; allocation inside kernel_launch is forbidden)
__device__ float g_xq[MROWS * DM];   // tf32-rounded Qin
__device__ float g_xk[MROWS * DM];   // tf32-rounded Kin
__device__ float g_xv[MROWS * DM];   // tf32-rounded Vin
__device__ float g_wq[DM * DM];      // tf32-rounded weights
__device__ float g_wk[DM * DM];
__device__ float g_wv[DM * DM];
__device__ float g_wo[DM * DM];
__device__ float g_q[MROWS * DM];    // projections (tf32-rounded values)
__device__ float g_k[MROWS * DM];
__device__ float g_v[MROWS * DM];
__device__ float g_ctx[MROWS * DM];  // tf32-rounded context
__device__ float g_y[MROWS * DM];    // pre-LN (fp32)
__device__ float g_attn[ATTN_ELEMS]; // only used if attn not in d_out
__device__ unsigned char g_mask8[MASK_ELEMS];  // mask as u8 (canonical form)
__device__ int   g_mask_is_int32;

// ---------------------------------------------------------------------------
// tf32 + cp.async helpers
// ---------------------------------------------------------------------------
__device__ __forceinline__ float f2tf(float x) {
    unsigned u;
    asm("cvt.rna.tf32.f32 %0, %1;" : "=r"(u) : "f"(x));
    return __uint_as_float(u);
}
__device__ __forceinline__ float4 tf32x4(float4 v) {
    return make_float4(f2tf(v.x), f2tf(v.y), f2tf(v.z), f2tf(v.w));
}
__device__ __forceinline__ void cpa16(const void* smem_dst, const void* gmem_src) {
    unsigned d = (unsigned)__cvta_generic_to_shared(smem_dst);
    asm volatile("cp.async.ca.shared.global [%0], [%1], 16;" :: "r"(d), "l"(gmem_src));
}
#define CPC    asm volatile("cp.async.commit_group;")
#define CPW(n) asm volatile("cp.async.wait_group %0;" :: "n"(n))

#define MMA_TF32(d, a, b0, b1) \
    asm volatile("mma.sync.aligned.m16n8k8.row.col.f32.tf32.tf32.f32 " \
                 "{%0,%1,%2,%3}, {%4,%5,%6,%7}, {%8,%9}, {%0,%1,%2,%3};" \
                 : "+f"(d[0]), "+f"(d[1]), "+f"(d[2]), "+f"(d[3]) \
                 : "r"(a[0]), "r"(a[1]), "r"(a[2]), "r"(a[3]), "r"(b0), "r"(b1))

// ---------------------------------------------------------------------------
// Mask dtype detection + canonicalize to u8.
// ---------------------------------------------------------------------------
__global__ void detect_mask_kernel(const unsigned* m) {
    int ok = 1;
    for (int i = threadIdx.x; i < 1024; i += 32)
        if (m[i] > 1u) ok = 0;
    unsigned b = __ballot_sync(0xffffffffu, ok);
    if (threadIdx.x == 0) g_mask_is_int32 = (b == 0xffffffffu) ? 1 : 0;
}
__global__ void mask_to_u8_kernel(const void* __restrict__ mask) {
    size_t i = (size_t)blockIdx.x * blockDim.x + threadIdx.x;  // uchar4 id
    uchar4 o;
    if (g_mask_is_int32) {
        int4 v = ((const int4*)mask)[i];
        o = make_uchar4(v.x != 0, v.y != 0, v.z != 0, v.w != 0);
    } else {
        o = ((const uchar4*)mask)[i];
    }
    ((uchar4*)g_mask8)[i] = o;
}

// ---------------------------------------------------------------------------
// Pre-round operands to tf32 once.
// ---------------------------------------------------------------------------
__global__ void round_inputs_kernel(const float* __restrict__ Q,
                                    const float* __restrict__ K,
                                    const float* __restrict__ V) {
    const float* s = blockIdx.z == 0 ? Q : blockIdx.z == 1 ? K : V;
    float* d = blockIdx.z == 0 ? g_xq : blockIdx.z == 1 ? g_xk : g_xv;
    size_t i = (size_t)blockIdx.x * blockDim.x + threadIdx.x;
    ((float4*)d)[i] = tf32x4(((const float4*)s)[i]);
}
__global__ void round_weights_kernel(const float* __restrict__ Wq,
                                     const float* __restrict__ Wk,
                                     const float* __restrict__ Wv,
                                     const float* __restrict__ Wo) {
    const float* s = blockIdx.z == 0 ? Wq : blockIdx.z == 1 ? Wk :
                     blockIdx.z == 2 ? Wv : Wo;
    float* d = blockIdx.z == 0 ? g_wq : blockIdx.z == 1 ? g_wk :
               blockIdx.z == 2 ? g_wv : g_wo;
    size_t i = (size_t)blockIdx.x * blockDim.x + threadIdx.x;
    ((float4*)d)[i] = tf32x4(((const float4*)s)[i]);
}

// ---------------------------------------------------------------------------
// 3-stage cp.async pipelined tf32 GEMM body (operands pre-rounded to tf32).
// NT threads = NT/32 warps arranged MW x (NT/32/MW); warp tile (MF*16)x(NF*8).
// A smem: [m][20] — frag banks (20r + cq) % 32 all-distinct.
// B smem: [k][BNS], BNS % 32 == 8 — frag banks (8cq + r) % 32 all-distinct.
// ---------------------------------------------------------------------------
template<int NT, int MW, int MF, int NF, int BNS>
__device__ __forceinline__ void gemm_pipe(
    const float* __restrict__ A, int lda,
    const float* __restrict__ B, int ldb,
    int K, float* __restrict__ sm,
    float (&acc)[MF][NF][4])
{
    constexpr int NWARP = NT / 32;
    constexpr int BM = MW * MF * 16;
    constexpr int BN = (NWARP / MW) * NF * 8;
    constexpr int STG = BM * 20 + 16 * BNS;
    constexpr int LA = BM * 4 / NT;
    constexpr int LB = BN * 4 / NT;
    const int tid = threadIdx.x;
    const int lane = tid & 31, wid = tid >> 5;
    const int wm = (wid & (MW - 1)) * (MF * 16);
    const int wn = (wid / MW) * (NF * 8);
    const int r = lane >> 2, cq = lane & 3;
    const int nch = K / 16;

    auto issue = [&](int c) {
        float* As = sm + (c % 3) * STG;
        float* Bs = As + BM * 20;
        const int k0 = c * 16;
        #pragma unroll
        for (int i = 0; i < LA; i++) {
            int f = tid + i * NT;
            int m = f >> 2, k4 = (f & 3) << 2;
            cpa16(As + m * 20 + k4, A + (size_t)m * lda + k0 + k4);
        }
        #pragma unroll
        for (int i = 0; i < LB; i++) {
            int f = tid + i * NT;
            int k = f / (BN / 4), n4 = (f % (BN / 4)) << 2;
            cpa16(Bs + k * BNS + n4, B + (size_t)(k0 + k) * ldb + n4);
        }
    };

    issue(0); CPC;
    issue(1); CPC;
    for (int c = 0; c < nch; c++) {
        if (c + 2 < nch) {
            CPW(1);
            __syncthreads();
            issue(c + 2); CPC;
        } else {
            CPW(0);
            __syncthreads();
        }
        const unsigned* As = (const unsigned*)(sm + (c % 3) * STG);
        const unsigned* Bs = As + BM * 20;
        #pragma unroll
        for (int ks = 0; ks < 2; ks++) {
            const int cc = ks * 8 + cq;
            unsigned a[MF][4];
            #pragma unroll
            for (int mf = 0; mf < MF; mf++) {
                const unsigned* p = As + (wm + mf * 16 + r) * 20 + cc;
                a[mf][0] = p[0];
                a[mf][1] = p[8 * 20];
                a[mf][2] = p[4];
                a[mf][3] = p[8 * 20 + 4];
            }
            #pragma unroll
            for (int nf = 0; nf < NF; nf++) {
                const int n = wn + nf * 8 + r;
                unsigned b0 = Bs[cc * BNS + n];
                unsigned b1 = Bs[(cc + 4) * BNS + n];
                #pragma unroll
                for (int mf = 0; mf < MF; mf++) {
                    MMA_TF32(acc[mf][nf], a[mf], b0, b1);
                }
            }
        }
    }
}

#define QKV_SMEM_BYTES  (3 * (128 * 20 + 16 * 136) * 4)   // 56832 (2 CTAs/SM)
#define CTX_SMEM_BYTES  (3 * (256 * 20 + 16 * 72) * 4)    // 75264

// ---------------------------------------------------------------------------
// 1) Fused QKV projections (NN): M=4096, N=1024, K=1024. Grid (8, 32, 3).
//    128 threads = 4 warps of 64x64; BM=128, BN=128; 2 CTAs/SM. (R12 proven.)
// ---------------------------------------------------------------------------
__global__ __launch_bounds__(128, 2) void qkv_gemm(
    const float* __restrict__ bq, const float* __restrict__ bk,
    const float* __restrict__ bv)
{
    extern __shared__ float sm[];
    const float* A; const float* W; const float* bias; float* C;
    if (blockIdx.z == 0)      { A = g_xq; W = g_wq; bias = bq; C = g_q; }
    else if (blockIdx.z == 1) { A = g_xk; W = g_wk; bias = bk; C = g_k; }
    else                      { A = g_xv; W = g_wv; bias = bv; C = g_v; }
    const int bm = blockIdx.y * 128, bn = blockIdx.x * 128;
    float acc[4][8][4] = {};
    gemm_pipe<128, 2, 4, 8, 136>(A + (size_t)bm * DM, DM, W + bn, DM, DM, sm, acc);

    const int lane = threadIdx.x & 31, wid = threadIdx.x >> 5;
    const int wm = (wid & 1) * 64, wn = (wid >> 1) * 64;
    const int r = lane >> 2, cq = lane & 3;
    #pragma unroll
    for (int mf = 0; mf < 4; mf++) {
        #pragma unroll
        for (int nf = 0; nf < 8; nf++) {
            int row = bm + wm + mf * 16 + r;
            int col = bn + wn + nf * 8 + 2 * cq;
            float2 bia = *(const float2*)&bias[col];
            *(float2*)&C[(size_t)row * DM + col] =
                make_float2(f2tf(acc[mf][nf][0] + bia.x), f2tf(acc[mf][nf][1] + bia.y));
            *(float2*)&C[(size_t)(row + 8) * DM + col] =
                make_float2(f2tf(acc[mf][nf][2] + bia.x), f2tf(acc[mf][nf][3] + bia.y));
        }
    }
}

// ---------------------------------------------------------------------------
// 2) FUSED scores + mask + softmax (mask read as u8 from g_mask8).
// ---------------------------------------------------------------------------
#define FUS_STRIDE 1028
#define FUS_SMEM_BYTES ((32 * FUS_STRIDE + 32 * 68 + 2 * 128 * 68) * 4)  // 209920

__global__ __launch_bounds__(256) void scores_softmax_kernel(
    float* __restrict__ attn_ext, int use_ext)
{
    extern __shared__ float sm[];
    float* Ss = sm;                          // [32][1028]
    float* Qs = Ss + 32 * FUS_STRIDE;        // [32][68]
    float* Ks = Qs + 32 * 68;                // 2 stages x [128][68]
    const int tid = threadIdx.x, lane = tid & 31, wid = tid >> 5;
    const int r = lane >> 2, cq = lane & 3;
    const int bh = blockIdx.y, b = bh >> 4, h = bh & 15;
    const int i0 = blockIdx.x * 32;
    const float* qb = g_q + (size_t)b * SS * DM + h * DH + (size_t)i0 * DM;
    const float* kb = g_k + (size_t)b * SS * DM + h * DH;

    #pragma unroll
    for (int i = 0; i < 2; i++) {
        int f = tid + i * 256;
        int m = f >> 4, k4 = (f & 15) << 2;
        cpa16(Qs + m * 68 + k4, qb + (size_t)m * DM + k4);
    }
    auto issueK = [&](int jt) {
        float* Kst = Ks + (jt & 1) * (128 * 68);
        const float* kbj = kb + (size_t)jt * 128 * DM;
        #pragma unroll
        for (int i = 0; i < 8; i++) {
            int f = tid + i * 256;
            int m = f >> 4, k4 = (f & 15) << 2;
            cpa16(Kst + m * 68 + k4, kbj + (size_t)m * DM + k4);
        }
    };
    issueK(0); CPC;

    const int wm = (wid & 1) * 16, wn = (wid >> 1) * 32;
    for (int jt = 0; jt < 8; jt++) {
        if (jt < 7) { issueK(jt + 1); CPC; CPW(1); }
        else        { CPW(0); }
        __syncthreads();
        const unsigned* Qu = (const unsigned*)Qs;
        const unsigned* Ku = (const unsigned*)(Ks + (jt & 1) * (128 * 68));
        float acc[4][4] = {};
        #pragma unroll
        for (int kc = 0; kc < 8; kc++) {
            const int cc = kc * 8 + cq;
            unsigned a[4];
            const unsigned* pa = Qu + (wm + r) * 68 + cc;
            a[0] = pa[0]; a[1] = pa[8 * 68]; a[2] = pa[4]; a[3] = pa[8 * 68 + 4];
            #pragma unroll
            for (int nf = 0; nf < 4; nf++) {
                const unsigned* pb = Ku + (wn + nf * 8 + r) * 68 + cc;
                MMA_TF32(acc[nf], a, pb[0], pb[4]);
            }
        }
        #pragma unroll
        for (int nf = 0; nf < 4; nf++) {
            int col = jt * 128 + wn + nf * 8 + 2 * cq;
            *(float2*)&Ss[(wm + r) * FUS_STRIDE + col] =
                make_float2(acc[nf][0], acc[nf][1]);
            *(float2*)&Ss[(wm + r + 8) * FUS_STRIDE + col] =
                make_float2(acc[nf][2], acc[nf][3]);
        }
        __syncthreads();
    }

    float* attn = use_ext ? attn_ext : g_attn;
    #pragma unroll
    for (int rl = 0; rl < 4; rl++) {
        int row = wid * 4 + rl;
        size_t mbase = (size_t)b * SS * SS + (size_t)(i0 + row) * SS;
        float mx = -3.4e38f;
        #pragma unroll
        for (int it = 0; it < 8; it++) {
            int c0 = (it * 32 + lane) * 4;
            float4 s4 = *(float4*)&Ss[row * FUS_STRIDE + c0];
            uchar4 u = *(const uchar4*)(g_mask8 + mbase + c0);
            s4.x = u.x ? -1e9f : s4.x * 0.125f;
            s4.y = u.y ? -1e9f : s4.y * 0.125f;
            s4.z = u.z ? -1e9f : s4.z * 0.125f;
            s4.w = u.w ? -1e9f : s4.w * 0.125f;
            *(float4*)&Ss[row * FUS_STRIDE + c0] = s4;
            mx = fmaxf(mx, fmaxf(fmaxf(s4.x, s4.y), fmaxf(s4.z, s4.w)));
        }
        #pragma unroll
        for (int o = 16; o; o >>= 1) mx = fmaxf(mx, __shfl_xor_sync(0xffffffffu, mx, o));
        float M = __shfl_sync(0xffffffffu, mx, 0);

        float s = 0.f;
        #pragma unroll
        for (int it = 0; it < 8; it++) {
            int c0 = (it * 32 + lane) * 4;
            float4 v = *(float4*)&Ss[row * FUS_STRIDE + c0];
            v.x = __expf(v.x - M); v.y = __expf(v.y - M);
            v.z = __expf(v.z - M); v.w = __expf(v.w - M);
            *(float4*)&Ss[row * FUS_STRIDE + c0] = v;
            s += v.x + v.y + v.z + v.w;
        }
        #pragma unroll
        for (int o = 16; o; o >>= 1) s += __shfl_xor_sync(0xffffffffu, s, o);
        float inv = 1.0f / s;

        size_t abase = (size_t)bh * SS * SS + (size_t)(i0 + row) * SS;
        #pragma unroll
        for (int it = 0; it < 8; it++) {
            int c0 = (it * 32 + lane) * 4;
            float4 v = *(float4*)&Ss[row * FUS_STRIDE + c0];
            *(float4*)&attn[abase + c0] =
                make_float4(f2tf(v.x * inv), f2tf(v.y * inv),
                            f2tf(v.z * inv), f2tf(v.w * inv));
        }
    }
}

// ---------------------------------------------------------------------------
// 3) Context (NN): per bh M=1024, N=64, K=1024. Grid (1, 4, 64). (R7 proven.)
// ---------------------------------------------------------------------------
__global__ __launch_bounds__(256) void context_kernel(const float* __restrict__ attn_ext, int use_ext) {
    extern __shared__ float sm[];
    const int bh = blockIdx.z, b = bh >> 4, h = bh & 15;
    const int bi = blockIdx.y * 256;
    const float* attn = use_ext ? attn_ext : g_attn;
    const float* ab = attn + (size_t)bh * SS * SS + (size_t)bi * SS;
    const float* vb = g_v + (size_t)b * SS * DM + h * DH;
    float acc[4][4][4] = {};
    gemm_pipe<256, 4, 4, 4, 72>(ab, SS, vb, DM, SS, sm, acc);

    const int lane = threadIdx.x & 31, wid = threadIdx.x >> 5;
    const int wm = (wid & 3) * 64, wn = (wid >> 2) * 32;
    const int r = lane >> 2, cq = lane & 3;
    float* cb = g_ctx + (size_t)b * SS * DM + h * DH;
    #pragma unroll
    for (int mf = 0; mf < 4; mf++) {
        #pragma unroll
        for (int nf = 0; nf < 4; nf++) {
            int row = bi + wm + mf * 16 + r;
            int col = wn + nf * 8 + 2 * cq;
            *(float2*)&cb[(size_t)row * DM + col] =
                make_float2(f2tf(acc[mf][nf][0]), f2tf(acc[mf][nf][1]));
            *(float2*)&cb[(size_t)(row + 8) * DM + col] =
                make_float2(f2tf(acc[mf][nf][2]), f2tf(acc[mf][nf][3]));
        }
    }
}

// ---------------------------------------------------------------------------
// 4) Output projection + residual (NN). Grid (8, 32), 128 thr, 2 CTAs/SM.
// ---------------------------------------------------------------------------
__global__ __launch_bounds__(128, 2) void outproj_kernel(
    const float* __restrict__ bo, const float* __restrict__ Qres)
{
    extern __shared__ float sm[];
    const int bm = blockIdx.y * 128, bn = blockIdx.x * 128;
    float acc[4][8][4] = {};
    gemm_pipe<128, 2, 4, 8, 136>(g_ctx + (size_t)bm * DM, DM, g_wo + bn, DM, DM, sm, acc);

    const int lane = threadIdx.x & 31, wid = threadIdx.x >> 5;
    const int wm = (wid & 1) * 64, wn = (wid >> 1) * 64;
    const int r = lane >> 2, cq = lane & 3;
    #pragma unroll
    for (int mf = 0; mf < 4; mf++) {
        #pragma unroll
        for (int nf = 0; nf < 8; nf++) {
            int row = bm + wm + mf * 16 + r;
            int col = bn + wn + nf * 8 + 2 * cq;
            float2 bia = *(const float2*)&bo[col];
            float2 q0 = *(const float2*)&Qres[(size_t)row * DM + col];
            float2 q1 = *(const float2*)&Qres[(size_t)(row + 8) * DM + col];
            *(float2*)&g_y[(size_t)row * DM + col] =
                make_float2(acc[mf][nf][0] + bia.x + q0.x, acc[mf][nf][1] + bia.y + q0.y);
            *(float2*)&g_y[(size_t)(row + 8) * DM + col] =
                make_float2(acc[mf][nf][2] + bia.x + q1.x, acc[mf][nf][3] + bia.y + q1.y);
        }
    }
}

// ---------------------------------------------------------------------------
// 5) LayerNorm over last dim (1024), biased variance, eps 1e-5. Grid 4096x256.
// ---------------------------------------------------------------------------
__global__ __launch_bounds__(256) void ln_kernel(
    const float* __restrict__ gamma, const float* __restrict__ beta,
    float* __restrict__ out)
{
    const float4* row = (const float4*)(g_y + (size_t)blockIdx.x * DM);
    const int t = threadIdx.x, lane = t & 31, w = t >> 5;
    __shared__ float s1[8], s2[8];
    float4 x = row[t];
    float a = x.x + x.y + x.z + x.w;
    float b = x.x * x.x + x.y * x.y + x.z * x.z + x.w * x.w;
    #pragma unroll
    for (int o = 16; o > 0; o >>= 1) {
        a += __shfl_xor_sync(0xffffffffu, a, o);
        b += __shfl_xor_sync(0xffffffffu, b, o);
    }
    if (lane == 0) { s1[w] = a; s2[w] = b; }
    __syncthreads();
    float A = 0.f, B2 = 0.f;
    #pragma unroll
    for (int i = 0; i < 8; i++) { A += s1[i]; B2 += s2[i]; }
    float mean = A * (1.0f / 1024.0f);
    float var = B2 * (1.0f / 1024.0f) - mean * mean;
    float rstd = rsqrtf(var + 1e-5f);
    float4 g = ((const float4*)gamma)[t];
    float4 be = ((const float4*)beta)[t];
    float4 o4;
    o4.x = (x.x - mean) * rstd * g.x + be.x;
    o4.y = (x.y - mean) * rstd * g.y + be.y;
    o4.z = (x.z - mean) * rstd * g.z + be.z;
    o4.w = (x.w - mean) * rstd * g.w + be.w;
    ((float4*)(out + (size_t)blockIdx.x * DM))[t] = o4;
}

// ---------------------------------------------------------------------------
extern "C" void kernel_launch(void* const* d_in, const int* in_sizes, int n_in,
                              void* d_out, int out_size) {
    const float* Qin   = (const float*)d_in[0];
    const void*  mask  = d_in[3];
    const float* Wq    = (const float*)d_in[4];
    const float* bq    = (const float*)d_in[5];
    const float* Wk    = (const float*)d_in[6];
    const float* bk    = (const float*)d_in[7];
    const float* Wv    = (const float*)d_in[8];
    const float* bv    = (const float*)d_in[9];
    const float* Wo    = (const float*)d_in[10];
    const float* bo    = (const float*)d_in[11];
    const float* gamma = (const float*)d_in[12];
    const float* beta  = (const float*)d_in[13];
    float* out = (float*)d_out;

    const int use_ext = (out_size > OUT_ELEMS) ? 1 : 0;
    float* attn_ext = out + OUT_ELEMS;

    cudaFuncSetAttribute(qkv_gemm, cudaFuncAttributeMaxDynamicSharedMemorySize, QKV_SMEM_BYTES);
    cudaFuncSetAttribute(outproj_kernel, cudaFuncAttributeMaxDynamicSharedMemorySize, QKV_SMEM_BYTES);
    cudaFuncSetAttribute(scores_softmax_kernel, cudaFuncAttributeMaxDynamicSharedMemorySize, FUS_SMEM_BYTES);
    cudaFuncSetAttribute(context_kernel, cudaFuncAttributeMaxDynamicSharedMemorySize, CTX_SMEM_BYTES);

    detect_mask_kernel<<<1, 32>>>((const unsigned*)mask);
    mask_to_u8_kernel<<<dim3(MASK_ELEMS / 4 / 256), 256>>>(mask);
    round_inputs_kernel<<<dim3(MROWS * DM / 4 / 256, 1, 3), 256>>>(
        Qin, (const float*)d_in[1], (const float*)d_in[2]);
    round_weights_kernel<<<dim3(DM * DM / 4 / 256, 1, 4), 256>>>(Wq, Wk, Wv, Wo);
    qkv_gemm<<<dim3(8, 32, 3), 128, QKV_SMEM_BYTES>>>(bq, bk, bv);
    scores_softmax_kernel<<<dim3(32, 64), 256, FUS_SMEM_BYTES>>>(attn_ext, use_ext);
    context_kernel<<<dim3(1, 4, 64), 256, CTX_SMEM_BYTES>>>(attn_ext, use_ext);
    outproj_kernel<<<dim3(8, 32), 128, QKV_SMEM_BYTES>>>(bo, Qin);
    ln_kernel<<<dim3(MROWS), 256>>>(gamma, beta, out);
    (void)in_sizes; (void)n_in;
}

// round 15
// speedup vs baseline: 1.0812x; 1.0022x over previous
#include <cuda_runtime.h>

// Problem constants
#define BI 4
#define SS 1024
#define DM 1024
#define NH 16
#define DH 64
#define MROWS (BI * SS)            // 4096
#define OUT_ELEMS (MROWS * DM)     // 4194304
#define ATTN_ELEMS ((size_t)BI * NH * SS * SS)
#define MASK_ELEMS ((size_t)BI * SS * SS)      // 4194304

// Scratch (device globals; allocation inside kernel_launch is forbidden)
__device__ float g_xq[MROWS * DM];   // tf32-rounded Qin
__device__ float g_xk[MROWS * DM];   // tf32-rounded Kin
__device__ float g_xv[MROWS * DM];   // tf32-rounded Vin
__device__ float g_wq[DM * DM];      // tf32-rounded weights
__device__ float g_wk[DM * DM];
__device__ float g_wv[DM * DM];
__device__ float g_wo[DM * DM];
__device__ float g_q[MROWS * DM];    // projections (tf32-rounded values)
__device__ float g_k[MROWS * DM];
__device__ float g_v[MROWS * DM];
__device__ float g_ctx[MROWS * DM];  // tf32-rounded context
__device__ float g_y[MROWS * DM];    // pre-LN (fp32)
__device__ float g_attn[ATTN_ELEMS]; // only used if attn not in d_out
__device__ unsigned char g_mask8[MASK_ELEMS];  // mask as u8 (canonical form)
__device__ int   g_mask_is_int32;

// ---------------------------------------------------------------------------
// tf32 + cp.async helpers
// ---------------------------------------------------------------------------
__device__ __forceinline__ float f2tf(float x) {
    unsigned u;
    asm("cvt.rna.tf32.f32 %0, %1;" : "=r"(u) : "f"(x));
    return __uint_as_float(u);
}
__device__ __forceinline__ float4 tf32x4(float4 v) {
    return make_float4(f2tf(v.x), f2tf(v.y), f2tf(v.z), f2tf(v.w));
}
__device__ __forceinline__ void cpa16(const void* smem_dst, const void* gmem_src) {
    unsigned d = (unsigned)__cvta_generic_to_shared(smem_dst);
    asm volatile("cp.async.ca.shared.global [%0], [%1], 16;" :: "r"(d), "l"(gmem_src));
}
#define CPC    asm volatile("cp.async.commit_group;")
#define CPW(n) asm volatile("cp.async.wait_group %0;" :: "n"(n))

#define MMA_TF32(d, a, b0, b1) \
    asm volatile("mma.sync.aligned.m16n8k8.row.col.f32.tf32.tf32.f32 " \
                 "{%0,%1,%2,%3}, {%4,%5,%6,%7}, {%8,%9}, {%0,%1,%2,%3};" \
                 : "+f"(d[0]), "+f"(d[1]), "+f"(d[2]), "+f"(d[3]) \
                 : "r"(a[0]), "r"(a[1]), "r"(a[2]), "r"(a[3]), "r"(b0), "r"(b1))

// ---------------------------------------------------------------------------
// Mask dtype detection.
// ---------------------------------------------------------------------------
__global__ void detect_mask_kernel(const unsigned* m) {
    int ok = 1;
    for (int i = threadIdx.x; i < 1024; i += 32)
        if (m[i] > 1u) ok = 0;
    unsigned b = __ballot_sync(0xffffffffu, ok);
    if (threadIdx.x == 0) g_mask_is_int32 = (b == 0xffffffffu) ? 1 : 0;
}

// ---------------------------------------------------------------------------
// Consolidated prep: tf32-round inputs & weights, canonicalize mask to u8.
// Linear block partition: [0,12288) inputs (3 x 4096), [12288,16384) weights
// (4 x 1024), [16384,20480) mask (4096). 256 threads, float4/uchar4 lanes.
// ---------------------------------------------------------------------------
__global__ __launch_bounds__(256) void prep_kernel(
    const float* __restrict__ Q, const float* __restrict__ K,
    const float* __restrict__ V,
    const float* __restrict__ Wq, const float* __restrict__ Wk,
    const float* __restrict__ Wv, const float* __restrict__ Wo,
    const void* __restrict__ mask)
{
    const int bid = blockIdx.x;
    if (bid < 12288) {
        const int z = bid >> 12;               // /4096
        const float* s = z == 0 ? Q : z == 1 ? K : V;
        float* d = z == 0 ? g_xq : z == 1 ? g_xk : g_xv;
        size_t i = (size_t)(bid & 4095) * 256 + threadIdx.x;
        ((float4*)d)[i] = tf32x4(((const float4*)s)[i]);
    } else if (bid < 16384) {
        const int t = bid - 12288;
        const int z = t >> 10;                 // /1024
        const float* s = z == 0 ? Wq : z == 1 ? Wk : z == 2 ? Wv : Wo;
        float* d = z == 0 ? g_wq : z == 1 ? g_wk : z == 2 ? g_wv : g_wo;
        size_t i = (size_t)(t & 1023) * 256 + threadIdx.x;
        ((float4*)d)[i] = tf32x4(((const float4*)s)[i]);
    } else {
        size_t i = (size_t)(bid - 16384) * 256 + threadIdx.x;
        uchar4 o;
        if (g_mask_is_int32) {
            int4 v = ((const int4*)mask)[i];
            o = make_uchar4(v.x != 0, v.y != 0, v.z != 0, v.w != 0);
        } else {
            o = ((const uchar4*)mask)[i];
        }
        ((uchar4*)g_mask8)[i] = o;
    }
}

// ---------------------------------------------------------------------------
// 3-stage cp.async pipelined tf32 GEMM body (operands pre-rounded to tf32).
// NT threads = NT/32 warps arranged MW x (NT/32/MW); warp tile (MF*16)x(NF*8).
// A smem: [m][20] — frag banks (20r + cq) % 32 all-distinct.
// B smem: [k][BNS], BNS % 32 == 8 — frag banks (8cq + r) % 32 all-distinct.
// ---------------------------------------------------------------------------
template<int NT, int MW, int MF, int NF, int BNS>
__device__ __forceinline__ void gemm_pipe(
    const float* __restrict__ A, int lda,
    const float* __restrict__ B, int ldb,
    int K, float* __restrict__ sm,
    float (&acc)[MF][NF][4])
{
    constexpr int NWARP = NT / 32;
    constexpr int BM = MW * MF * 16;
    constexpr int BN = (NWARP / MW) * NF * 8;
    constexpr int STG = BM * 20 + 16 * BNS;
    constexpr int LA = BM * 4 / NT;
    constexpr int LB = BN * 4 / NT;
    const int tid = threadIdx.x;
    const int lane = tid & 31, wid = tid >> 5;
    const int wm = (wid & (MW - 1)) * (MF * 16);
    const int wn = (wid / MW) * (NF * 8);
    const int r = lane >> 2, cq = lane & 3;
    const int nch = K / 16;

    auto issue = [&](int c) {
        float* As = sm + (c % 3) * STG;
        float* Bs = As + BM * 20;
        const int k0 = c * 16;
        #pragma unroll
        for (int i = 0; i < LA; i++) {
            int f = tid + i * NT;
            int m = f >> 2, k4 = (f & 3) << 2;
            cpa16(As + m * 20 + k4, A + (size_t)m * lda + k0 + k4);
        }
        #pragma unroll
        for (int i = 0; i < LB; i++) {
            int f = tid + i * NT;
            int k = f / (BN / 4), n4 = (f % (BN / 4)) << 2;
            cpa16(Bs + k * BNS + n4, B + (size_t)(k0 + k) * ldb + n4);
        }
    };

    issue(0); CPC;
    issue(1); CPC;
    for (int c = 0; c < nch; c++) {
        if (c + 2 < nch) {
            CPW(1);
            __syncthreads();
            issue(c + 2); CPC;
        } else {
            CPW(0);
            __syncthreads();
        }
        const unsigned* As = (const unsigned*)(sm + (c % 3) * STG);
        const unsigned* Bs = As + BM * 20;
        #pragma unroll
        for (int ks = 0; ks < 2; ks++) {
            const int cc = ks * 8 + cq;
            unsigned a[MF][4];
            #pragma unroll
            for (int mf = 0; mf < MF; mf++) {
                const unsigned* p = As + (wm + mf * 16 + r) * 20 + cc;
                a[mf][0] = p[0];
                a[mf][1] = p[8 * 20];
                a[mf][2] = p[4];
                a[mf][3] = p[8 * 20 + 4];
            }
            #pragma unroll
            for (int nf = 0; nf < NF; nf++) {
                const int n = wn + nf * 8 + r;
                unsigned b0 = Bs[cc * BNS + n];
                unsigned b1 = Bs[(cc + 4) * BNS + n];
                #pragma unroll
                for (int mf = 0; mf < MF; mf++) {
                    MMA_TF32(acc[mf][nf], a[mf], b0, b1);
                }
            }
        }
    }
}

#define QKV_SMEM_BYTES  (3 * (128 * 20 + 16 * 136) * 4)   // 56832 (2 CTAs/SM)
#define CTX_SMEM_BYTES  (3 * (256 * 20 + 16 * 72) * 4)    // 75264 (2 CTAs/SM)

// ---------------------------------------------------------------------------
// 1) Fused QKV projections (NN): M=4096, N=1024, K=1024. Grid (8, 32, 3).
//    128 threads = 4 warps of 64x64; BM=128, BN=128; 2 CTAs/SM. (R12 proven.)
// ---------------------------------------------------------------------------
__global__ __launch_bounds__(128, 2) void qkv_gemm(
    const float* __restrict__ bq, const float* __restrict__ bk,
    const float* __restrict__ bv)
{
    extern __shared__ float sm[];
    const float* A; const float* W; const float* bias; float* C;
    if (blockIdx.z == 0)      { A = g_xq; W = g_wq; bias = bq; C = g_q; }
    else if (blockIdx.z == 1) { A = g_xk; W = g_wk; bias = bk; C = g_k; }
    else                      { A = g_xv; W = g_wv; bias = bv; C = g_v; }
    const int bm = blockIdx.y * 128, bn = blockIdx.x * 128;
    float acc[4][8][4] = {};
    gemm_pipe<128, 2, 4, 8, 136>(A + (size_t)bm * DM, DM, W + bn, DM, DM, sm, acc);

    const int lane = threadIdx.x & 31, wid = threadIdx.x >> 5;
    const int wm = (wid & 1) * 64, wn = (wid >> 1) * 64;
    const int r = lane >> 2, cq = lane & 3;
    #pragma unroll
    for (int mf = 0; mf < 4; mf++) {
        #pragma unroll
        for (int nf = 0; nf < 8; nf++) {
            int row = bm + wm + mf * 16 + r;
            int col = bn + wn + nf * 8 + 2 * cq;
            float2 bia = *(const float2*)&bias[col];
            *(float2*)&C[(size_t)row * DM + col] =
                make_float2(f2tf(acc[mf][nf][0] + bia.x), f2tf(acc[mf][nf][1] + bia.y));
            *(float2*)&C[(size_t)(row + 8) * DM + col] =
                make_float2(f2tf(acc[mf][nf][2] + bia.x), f2tf(acc[mf][nf][3] + bia.y));
        }
    }
}

// ---------------------------------------------------------------------------
// 2) FUSED scores + mask + softmax (mask read as u8 from g_mask8).
// ---------------------------------------------------------------------------
#define FUS_STRIDE 1028
#define FUS_SMEM_BYTES ((32 * FUS_STRIDE + 32 * 68 + 2 * 128 * 68) * 4)  // 209920

__global__ __launch_bounds__(256) void scores_softmax_kernel(
    float* __restrict__ attn_ext, int use_ext)
{
    extern __shared__ float sm[];
    float* Ss = sm;                          // [32][1028]
    float* Qs = Ss + 32 * FUS_STRIDE;        // [32][68]
    float* Ks = Qs + 32 * 68;                // 2 stages x [128][68]
    const int tid = threadIdx.x, lane = tid & 31, wid = tid >> 5;
    const int r = lane >> 2, cq = lane & 3;
    const int bh = blockIdx.y, b = bh >> 4, h = bh & 15;
    const int i0 = blockIdx.x * 32;
    const float* qb = g_q + (size_t)b * SS * DM + h * DH + (size_t)i0 * DM;
    const float* kb = g_k + (size_t)b * SS * DM + h * DH;

    #pragma unroll
    for (int i = 0; i < 2; i++) {
        int f = tid + i * 256;
        int m = f >> 4, k4 = (f & 15) << 2;
        cpa16(Qs + m * 68 + k4, qb + (size_t)m * DM + k4);
    }
    auto issueK = [&](int jt) {
        float* Kst = Ks + (jt & 1) * (128 * 68);
        const float* kbj = kb + (size_t)jt * 128 * DM;
        #pragma unroll
        for (int i = 0; i < 8; i++) {
            int f = tid + i * 256;
            int m = f >> 4, k4 = (f & 15) << 2;
            cpa16(Kst + m * 68 + k4, kbj + (size_t)m * DM + k4);
        }
    };
    issueK(0); CPC;

    const int wm = (wid & 1) * 16, wn = (wid >> 1) * 32;
    for (int jt = 0; jt < 8; jt++) {
        if (jt < 7) { issueK(jt + 1); CPC; CPW(1); }
        else        { CPW(0); }
        __syncthreads();
        const unsigned* Qu = (const unsigned*)Qs;
        const unsigned* Ku = (const unsigned*)(Ks + (jt & 1) * (128 * 68));
        float acc[4][4] = {};
        #pragma unroll
        for (int kc = 0; kc < 8; kc++) {
            const int cc = kc * 8 + cq;
            unsigned a[4];
            const unsigned* pa = Qu + (wm + r) * 68 + cc;
            a[0] = pa[0]; a[1] = pa[8 * 68]; a[2] = pa[4]; a[3] = pa[8 * 68 + 4];
            #pragma unroll
            for (int nf = 0; nf < 4; nf++) {
                const unsigned* pb = Ku + (wn + nf * 8 + r) * 68 + cc;
                MMA_TF32(acc[nf], a, pb[0], pb[4]);
            }
        }
        #pragma unroll
        for (int nf = 0; nf < 4; nf++) {
            int col = jt * 128 + wn + nf * 8 + 2 * cq;
            *(float2*)&Ss[(wm + r) * FUS_STRIDE + col] =
                make_float2(acc[nf][0], acc[nf][1]);
            *(float2*)&Ss[(wm + r + 8) * FUS_STRIDE + col] =
                make_float2(acc[nf][2], acc[nf][3]);
        }
        __syncthreads();
    }

    float* attn = use_ext ? attn_ext : g_attn;
    #pragma unroll
    for (int rl = 0; rl < 4; rl++) {
        int row = wid * 4 + rl;
        size_t mbase = (size_t)b * SS * SS + (size_t)(i0 + row) * SS;
        float mx = -3.4e38f;
        #pragma unroll
        for (int it = 0; it < 8; it++) {
            int c0 = (it * 32 + lane) * 4;
            float4 s4 = *(float4*)&Ss[row * FUS_STRIDE + c0];
            uchar4 u = *(const uchar4*)(g_mask8 + mbase + c0);
            s4.x = u.x ? -1e9f : s4.x * 0.125f;
            s4.y = u.y ? -1e9f : s4.y * 0.125f;
            s4.z = u.z ? -1e9f : s4.z * 0.125f;
            s4.w = u.w ? -1e9f : s4.w * 0.125f;
            *(float4*)&Ss[row * FUS_STRIDE + c0] = s4;
            mx = fmaxf(mx, fmaxf(fmaxf(s4.x, s4.y), fmaxf(s4.z, s4.w)));
        }
        #pragma unroll
        for (int o = 16; o; o >>= 1) mx = fmaxf(mx, __shfl_xor_sync(0xffffffffu, mx, o));
        float M = __shfl_sync(0xffffffffu, mx, 0);

        float s = 0.f;
        #pragma unroll
        for (int it = 0; it < 8; it++) {
            int c0 = (it * 32 + lane) * 4;
            float4 v = *(float4*)&Ss[row * FUS_STRIDE + c0];
            v.x = __expf(v.x - M); v.y = __expf(v.y - M);
            v.z = __expf(v.z - M); v.w = __expf(v.w - M);
            *(float4*)&Ss[row * FUS_STRIDE + c0] = v;
            s += v.x + v.y + v.z + v.w;
        }
        #pragma unroll
        for (int o = 16; o; o >>= 1) s += __shfl_xor_sync(0xffffffffu, s, o);
        float inv = 1.0f / s;

        size_t abase = (size_t)bh * SS * SS + (size_t)(i0 + row) * SS;
        #pragma unroll
        for (int it = 0; it < 8; it++) {
            int c0 = (it * 32 + lane) * 4;
            float4 v = *(float4*)&Ss[row * FUS_STRIDE + c0];
            *(float4*)&attn[abase + c0] =
                make_float4(f2tf(v.x * inv), f2tf(v.y * inv),
                            f2tf(v.z * inv), f2tf(v.w * inv));
        }
    }
}

// ---------------------------------------------------------------------------
// 3) Context (NN): per bh M=1024, N=64, K=1024. Grid (1, 4, 64).
//    Now pinned to 2 CTAs/SM (regs capped at 128).
// ---------------------------------------------------------------------------
__global__ __launch_bounds__(256, 2) void context_kernel(const float* __restrict__ attn_ext, int use_ext) {
    extern __shared__ float sm[];
    const int bh = blockIdx.z, b = bh >> 4, h = bh & 15;
    const int bi = blockIdx.y * 256;
    const float* attn = use_ext ? attn_ext : g_attn;
    const float* ab = attn + (size_t)bh * SS * SS + (size_t)bi * SS;
    const float* vb = g_v + (size_t)b * SS * DM + h * DH;
    float acc[4][4][4] = {};
    gemm_pipe<256, 4, 4, 4, 72>(ab, SS, vb, DM, SS, sm, acc);

    const int lane = threadIdx.x & 31, wid = threadIdx.x >> 5;
    const int wm = (wid & 3) * 64, wn = (wid >> 2) * 32;
    const int r = lane >> 2, cq = lane & 3;
    float* cb = g_ctx + (size_t)b * SS * DM + h * DH;
    #pragma unroll
    for (int mf = 0; mf < 4; mf++) {
        #pragma unroll
        for (int nf = 0; nf < 4; nf++) {
            int row = bi + wm + mf * 16 + r;
            int col = wn + nf * 8 + 2 * cq;
            *(float2*)&cb[(size_t)row * DM + col] =
                make_float2(f2tf(acc[mf][nf][0]), f2tf(acc[mf][nf][1]));
            *(float2*)&cb[(size_t)(row + 8) * DM + col] =
                make_float2(f2tf(acc[mf][nf][2]), f2tf(acc[mf][nf][3]));
        }
    }
}

// ---------------------------------------------------------------------------
// 4) Output projection + residual (NN). Grid (8, 32), 128 thr, 2 CTAs/SM.
// ---------------------------------------------------------------------------
__global__ __launch_bounds__(128, 2) void outproj_kernel(
    const float* __restrict__ bo, const float* __restrict__ Qres)
{
    extern __shared__ float sm[];
    const int bm = blockIdx.y * 128, bn = blockIdx.x * 128;
    float acc[4][8][4] = {};
    gemm_pipe<128, 2, 4, 8, 136>(g_ctx + (size_t)bm * DM, DM, g_wo + bn, DM, DM, sm, acc);

    const int lane = threadIdx.x & 31, wid = threadIdx.x >> 5;
    const int wm = (wid & 1) * 64, wn = (wid >> 1) * 64;
    const int r = lane >> 2, cq = lane & 3;
    #pragma unroll
    for (int mf = 0; mf < 4; mf++) {
        #pragma unroll
        for (int nf = 0; nf < 8; nf++) {
            int row = bm + wm + mf * 16 + r;
            int col = bn + wn + nf * 8 + 2 * cq;
            float2 bia = *(const float2*)&bo[col];
            float2 q0 = *(const float2*)&Qres[(size_t)row * DM + col];
            float2 q1 = *(const float2*)&Qres[(size_t)(row + 8) * DM + col];
            *(float2*)&g_y[(size_t)row * DM + col] =
                make_float2(acc[mf][nf][0] + bia.x + q0.x, acc[mf][nf][1] + bia.y + q0.y);
            *(float2*)&g_y[(size_t)(row + 8) * DM + col] =
                make_float2(acc[mf][nf][2] + bia.x + q1.x, acc[mf][nf][3] + bia.y + q1.y);
        }
    }
}

// ---------------------------------------------------------------------------
// 5) LayerNorm over last dim (1024), biased variance, eps 1e-5. Grid 4096x256.
// ---------------------------------------------------------------------------
__global__ __launch_bounds__(256) void ln_kernel(
    const float* __restrict__ gamma, const float* __restrict__ beta,
    float* __restrict__ out)
{
    const float4* row = (const float4*)(g_y + (size_t)blockIdx.x * DM);
    const int t = threadIdx.x, lane = t & 31, w = t >> 5;
    __shared__ float s1[8], s2[8];
    float4 x = row[t];
    float a = x.x + x.y + x.z + x.w;
    float b = x.x * x.x + x.y * x.y + x.z * x.z + x.w * x.w;
    #pragma unroll
    for (int o = 16; o > 0; o >>= 1) {
        a += __shfl_xor_sync(0xffffffffu, a, o);
        b += __shfl_xor_sync(0xffffffffu, b, o);
    }
    if (lane == 0) { s1[w] = a; s2[w] = b; }
    __syncthreads();
    float A = 0.f, B2 = 0.f;
    #pragma unroll
    for (int i = 0; i < 8; i++) { A += s1[i]; B2 += s2[i]; }
    float mean = A * (1.0f / 1024.0f);
    float var = B2 * (1.0f / 1024.0f) - mean * mean;
    float rstd = rsqrtf(var + 1e-5f);
    float4 g = ((const float4*)gamma)[t];
    float4 be = ((const float4*)beta)[t];
    float4 o4;
    o4.x = (x.x - mean) * rstd * g.x + be.x;
    o4.y = (x.y - mean) * rstd * g.y + be.y;
    o4.z = (x.z - mean) * rstd * g.z + be.z;
    o4.w = (x.w - mean) * rstd * g.w + be.w;
    ((float4*)(out + (size_t)blockIdx.x * DM))[t] = o4;
}

// ---------------------------------------------------------------------------
extern "C" void kernel_launch(void* const* d_in, const int* in_sizes, int n_in,
                              void* d_out, int out_size) {
    const float* Qin   = (const float*)d_in[0];
    const void*  mask  = d_in[3];
    const float* Wq    = (const float*)d_in[4];
    const float* bq    = (const float*)d_in[5];
    const float* Wk    = (const float*)d_in[6];
    const float* bk    = (const float*)d_in[7];
    const float* Wv    = (const float*)d_in[8];
    const float* bv    = (const float*)d_in[9];
    const float* Wo    = (const float*)d_in[10];
    const float* bo    = (const float*)d_in[11];
    const float* gamma = (const float*)d_in[12];
    const float* beta  = (const float*)d_in[13];
    float* out = (float*)d_out;

    const int use_ext = (out_size > OUT_ELEMS) ? 1 : 0;
    float* attn_ext = out + OUT_ELEMS;

    cudaFuncSetAttribute(qkv_gemm, cudaFuncAttributeMaxDynamicSharedMemorySize, QKV_SMEM_BYTES);
    cudaFuncSetAttribute(outproj_kernel, cudaFuncAttributeMaxDynamicSharedMemorySize, QKV_SMEM_BYTES);
    cudaFuncSetAttribute(scores_softmax_kernel, cudaFuncAttributeMaxDynamicSharedMemorySize, FUS_SMEM_BYTES);
    cudaFuncSetAttribute(context_kernel, cudaFuncAttributeMaxDynamicSharedMemorySize, CTX_SMEM_BYTES);

    detect_mask_kernel<<<1, 32>>>((const unsigned*)mask);
    prep_kernel<<<dim3(20480), 256>>>(
        Qin, (const float*)d_in[1], (const float*)d_in[2],
        Wq, Wk, Wv, Wo, mask);
    qkv_gemm<<<dim3(8, 32, 3), 128, QKV_SMEM_BYTES>>>(bq, bk, bv);
    scores_softmax_kernel<<<dim3(32, 64), 256, FUS_SMEM_BYTES>>>(attn_ext, use_ext);
    context_kernel<<<dim3(1, 4, 64), 256, CTX_SMEM_BYTES>>>(attn_ext, use_ext);
    outproj_kernel<<<dim3(8, 32), 128, QKV_SMEM_BYTES>>>(bo, Qin);
    ln_kernel<<<dim3(MROWS), 256>>>(gamma, beta, out);
    (void)in_sizes; (void)n_in;
}

// round 16
// speedup vs baseline: 1.0847x; 1.0032x over previous
#include <cuda_runtime.h>

// Problem constants
#define BI 4
#define SS 1024
#define DM 1024
#define NH 16
#define DH 64
#define MROWS (BI * SS)            // 4096
#define OUT_ELEMS (MROWS * DM)     // 4194304
#define ATTN_ELEMS ((size_t)BI * NH * SS * SS)
#define MASK_ELEMS ((size_t)BI * SS * SS)      // 4194304

// Scratch (device globals; allocation inside kernel_launch is forbidden)
__device__ float g_xq[MROWS * DM];   // tf32-rounded Qin
__device__ float g_xk[MROWS * DM];   // tf32-rounded Kin
__device__ float g_xv[MROWS * DM];   // tf32-rounded Vin
__device__ float g_wq[DM * DM];      // tf32-rounded weights
__device__ float g_wk[DM * DM];
__device__ float g_wv[DM * DM];
__device__ float g_wo[DM * DM];
__device__ float g_q[MROWS * DM];    // projections (tf32-rounded values)
__device__ float g_k[MROWS * DM];
__device__ float g_v[MROWS * DM];
__device__ float g_ctx[MROWS * DM];  // tf32-rounded context
__device__ float g_y[MROWS * DM];    // pre-LN (fp32)
__device__ float g_attn[ATTN_ELEMS]; // only used if attn not in d_out
__device__ unsigned char g_mask8[MASK_ELEMS];  // mask as u8 (canonical form)
__device__ int   g_mask_is_int32;

// ---------------------------------------------------------------------------
// tf32 + cp.async helpers
// ---------------------------------------------------------------------------
__device__ __forceinline__ float f2tf(float x) {
    unsigned u;
    asm("cvt.rna.tf32.f32 %0, %1;" : "=r"(u) : "f"(x));
    return __uint_as_float(u);
}
__device__ __forceinline__ float4 tf32x4(float4 v) {
    return make_float4(f2tf(v.x), f2tf(v.y), f2tf(v.z), f2tf(v.w));
}
__device__ __forceinline__ void cpa16(const void* smem_dst, const void* gmem_src) {
    unsigned d = (unsigned)__cvta_generic_to_shared(smem_dst);
    asm volatile("cp.async.ca.shared.global [%0], [%1], 16;" :: "r"(d), "l"(gmem_src));
}
#define CPC    asm volatile("cp.async.commit_group;")
#define CPW(n) asm volatile("cp.async.wait_group %0;" :: "n"(n))

#define MMA_TF32(d, a, b0, b1) \
    asm volatile("mma.sync.aligned.m16n8k8.row.col.f32.tf32.tf32.f32 " \
                 "{%0,%1,%2,%3}, {%4,%5,%6,%7}, {%8,%9}, {%0,%1,%2,%3};" \
                 : "+f"(d[0]), "+f"(d[1]), "+f"(d[2]), "+f"(d[3]) \
                 : "r"(a[0]), "r"(a[1]), "r"(a[2]), "r"(a[3]), "r"(b0), "r"(b1))

// ---------------------------------------------------------------------------
// Mask dtype detection.
// ---------------------------------------------------------------------------
__global__ void detect_mask_kernel(const unsigned* m) {
    int ok = 1;
    for (int i = threadIdx.x; i < 1024; i += 32)
        if (m[i] > 1u) ok = 0;
    unsigned b = __ballot_sync(0xffffffffu, ok);
    if (threadIdx.x == 0) g_mask_is_int32 = (b == 0xffffffffu) ? 1 : 0;
}

// ---------------------------------------------------------------------------
// Consolidated prep: tf32-round inputs & weights, canonicalize mask to u8.
// ---------------------------------------------------------------------------
__global__ __launch_bounds__(256) void prep_kernel(
    const float* __restrict__ Q, const float* __restrict__ K,
    const float* __restrict__ V,
    const float* __restrict__ Wq, const float* __restrict__ Wk,
    const float* __restrict__ Wv, const float* __restrict__ Wo,
    const void* __restrict__ mask)
{
    const int bid = blockIdx.x;
    if (bid < 12288) {
        const int z = bid >> 12;               // /4096
        const float* s = z == 0 ? Q : z == 1 ? K : V;
        float* d = z == 0 ? g_xq : z == 1 ? g_xk : g_xv;
        size_t i = (size_t)(bid & 4095) * 256 + threadIdx.x;
        ((float4*)d)[i] = tf32x4(((const float4*)s)[i]);
    } else if (bid < 16384) {
        const int t = bid - 12288;
        const int z = t >> 10;                 // /1024
        const float* s = z == 0 ? Wq : z == 1 ? Wk : z == 2 ? Wv : Wo;
        float* d = z == 0 ? g_wq : z == 1 ? g_wk : z == 2 ? g_wv : g_wo;
        size_t i = (size_t)(t & 1023) * 256 + threadIdx.x;
        ((float4*)d)[i] = tf32x4(((const float4*)s)[i]);
    } else {
        size_t i = (size_t)(bid - 16384) * 256 + threadIdx.x;
        uchar4 o;
        if (g_mask_is_int32) {
            int4 v = ((const int4*)mask)[i];
            o = make_uchar4(v.x != 0, v.y != 0, v.z != 0, v.w != 0);
        } else {
            o = ((const uchar4*)mask)[i];
        }
        ((uchar4*)g_mask8)[i] = o;
    }
}

// ---------------------------------------------------------------------------
// 3-stage cp.async pipelined tf32 GEMM body (operands pre-rounded to tf32).
// ---------------------------------------------------------------------------
template<int NT, int MW, int MF, int NF, int BNS>
__device__ __forceinline__ void gemm_pipe(
    const float* __restrict__ A, int lda,
    const float* __restrict__ B, int ldb,
    int K, float* __restrict__ sm,
    float (&acc)[MF][NF][4])
{
    constexpr int NWARP = NT / 32;
    constexpr int BM = MW * MF * 16;
    constexpr int BN = (NWARP / MW) * NF * 8;
    constexpr int STG = BM * 20 + 16 * BNS;
    constexpr int LA = BM * 4 / NT;
    constexpr int LB = BN * 4 / NT;
    const int tid = threadIdx.x;
    const int lane = tid & 31, wid = tid >> 5;
    const int wm = (wid & (MW - 1)) * (MF * 16);
    const int wn = (wid / MW) * (NF * 8);
    const int r = lane >> 2, cq = lane & 3;
    const int nch = K / 16;

    auto issue = [&](int c) {
        float* As = sm + (c % 3) * STG;
        float* Bs = As + BM * 20;
        const int k0 = c * 16;
        #pragma unroll
        for (int i = 0; i < LA; i++) {
            int f = tid + i * NT;
            int m = f >> 2, k4 = (f & 3) << 2;
            cpa16(As + m * 20 + k4, A + (size_t)m * lda + k0 + k4);
        }
        #pragma unroll
        for (int i = 0; i < LB; i++) {
            int f = tid + i * NT;
            int k = f / (BN / 4), n4 = (f % (BN / 4)) << 2;
            cpa16(Bs + k * BNS + n4, B + (size_t)(k0 + k) * ldb + n4);
        }
    };

    issue(0); CPC;
    issue(1); CPC;
    for (int c = 0; c < nch; c++) {
        if (c + 2 < nch) {
            CPW(1);
            __syncthreads();
            issue(c + 2); CPC;
        } else {
            CPW(0);
            __syncthreads();
        }
        const unsigned* As = (const unsigned*)(sm + (c % 3) * STG);
        const unsigned* Bs = As + BM * 20;
        #pragma unroll
        for (int ks = 0; ks < 2; ks++) {
            const int cc = ks * 8 + cq;
            unsigned a[MF][4];
            #pragma unroll
            for (int mf = 0; mf < MF; mf++) {
                const unsigned* p = As + (wm + mf * 16 + r) * 20 + cc;
                a[mf][0] = p[0];
                a[mf][1] = p[8 * 20];
                a[mf][2] = p[4];
                a[mf][3] = p[8 * 20 + 4];
            }
            #pragma unroll
            for (int nf = 0; nf < NF; nf++) {
                const int n = wn + nf * 8 + r;
                unsigned b0 = Bs[cc * BNS + n];
                unsigned b1 = Bs[(cc + 4) * BNS + n];
                #pragma unroll
                for (int mf = 0; mf < MF; mf++) {
                    MMA_TF32(acc[mf][nf], a[mf], b0, b1);
                }
            }
        }
    }
}

#define QKV_SMEM_BYTES  (3 * (128 * 20 + 16 * 136) * 4)   // 56832 (2 CTAs/SM)
#define CTX_SMEM_BYTES  (3 * (256 * 20 + 16 * 72) * 4)    // 75264 (2 CTAs/SM)

// ---------------------------------------------------------------------------
// 1) Fused QKV projections (NN): M=4096, N=1024, K=1024. Grid (8, 32, 3).
// ---------------------------------------------------------------------------
__global__ __launch_bounds__(128, 2) void qkv_gemm(
    const float* __restrict__ bq, const float* __restrict__ bk,
    const float* __restrict__ bv)
{
    extern __shared__ float sm[];
    const float* A; const float* W; const float* bias; float* C;
    if (blockIdx.z == 0)      { A = g_xq; W = g_wq; bias = bq; C = g_q; }
    else if (blockIdx.z == 1) { A = g_xk; W = g_wk; bias = bk; C = g_k; }
    else                      { A = g_xv; W = g_wv; bias = bv; C = g_v; }
    const int bm = blockIdx.y * 128, bn = blockIdx.x * 128;
    float acc[4][8][4] = {};
    gemm_pipe<128, 2, 4, 8, 136>(A + (size_t)bm * DM, DM, W + bn, DM, DM, sm, acc);

    const int lane = threadIdx.x & 31, wid = threadIdx.x >> 5;
    const int wm = (wid & 1) * 64, wn = (wid >> 1) * 64;
    const int r = lane >> 2, cq = lane & 3;
    #pragma unroll
    for (int mf = 0; mf < 4; mf++) {
        #pragma unroll
        for (int nf = 0; nf < 8; nf++) {
            int row = bm + wm + mf * 16 + r;
            int col = bn + wn + nf * 8 + 2 * cq;
            float2 bia = *(const float2*)&bias[col];
            *(float2*)&C[(size_t)row * DM + col] =
                make_float2(f2tf(acc[mf][nf][0] + bia.x), f2tf(acc[mf][nf][1] + bia.y));
            *(float2*)&C[(size_t)(row + 8) * DM + col] =
                make_float2(f2tf(acc[mf][nf][2] + bia.x), f2tf(acc[mf][nf][3] + bia.y));
        }
    }
}

// ---------------------------------------------------------------------------
// 2) FUSED scores + mask + softmax — now 512 threads (16 warps) per CTA.
// Phase 1 warp grid 2x8 (wm in {0,16}, 8 slices of 16 cols, NF=2).
// Softmax: 16 warps x 2 rows. Smem layout unchanged.
// ---------------------------------------------------------------------------
#define FUS_STRIDE 1028
#define FUS_SMEM_BYTES ((32 * FUS_STRIDE + 32 * 68 + 2 * 128 * 68) * 4)  // 209920

__global__ __launch_bounds__(512) void scores_softmax_kernel(
    float* __restrict__ attn_ext, int use_ext)
{
    extern __shared__ float sm[];
    float* Ss = sm;                          // [32][1028]
    float* Qs = Ss + 32 * FUS_STRIDE;        // [32][68]
    float* Ks = Qs + 32 * 68;                // 2 stages x [128][68]
    const int tid = threadIdx.x, lane = tid & 31, wid = tid >> 5;
    const int r = lane >> 2, cq = lane & 3;
    const int bh = blockIdx.y, b = bh >> 4, h = bh & 15;
    const int i0 = blockIdx.x * 32;
    const float* qb = g_q + (size_t)b * SS * DM + h * DH + (size_t)i0 * DM;
    const float* kb = g_k + (size_t)b * SS * DM + h * DH;

    // Q tile 32x64 floats = 512 float4 = 1 per thread
    {
        int m = tid >> 4, k4 = (tid & 15) << 2;
        cpa16(Qs + m * 68 + k4, qb + (size_t)m * DM + k4);
    }
    // K tile 128x64 floats = 2048 float4 = 4 per thread
    auto issueK = [&](int jt) {
        float* Kst = Ks + (jt & 1) * (128 * 68);
        const float* kbj = kb + (size_t)jt * 128 * DM;
        #pragma unroll
        for (int i = 0; i < 4; i++) {
            int f = tid + i * 512;
            int m = f >> 4, k4 = (f & 15) << 2;
            cpa16(Kst + m * 68 + k4, kbj + (size_t)m * DM + k4);
        }
    };
    issueK(0); CPC;

    // 16 warps: wm = (wid&1)*16, wn = (wid>>1)*16; NF=2
    const int wm = (wid & 1) * 16, wn = (wid >> 1) * 16;
    for (int jt = 0; jt < 8; jt++) {
        if (jt < 7) { issueK(jt + 1); CPC; CPW(1); }
        else        { CPW(0); }
        __syncthreads();
        const unsigned* Qu = (const unsigned*)Qs;
        const unsigned* Ku = (const unsigned*)(Ks + (jt & 1) * (128 * 68));
        float acc[2][4] = {};
        #pragma unroll
        for (int kc = 0; kc < 8; kc++) {
            const int cc = kc * 8 + cq;
            unsigned a[4];
            const unsigned* pa = Qu + (wm + r) * 68 + cc;
            a[0] = pa[0]; a[1] = pa[8 * 68]; a[2] = pa[4]; a[3] = pa[8 * 68 + 4];
            #pragma unroll
            for (int nf = 0; nf < 2; nf++) {
                const unsigned* pb = Ku + (wn + nf * 8 + r) * 68 + cc;
                MMA_TF32(acc[nf], a, pb[0], pb[4]);
            }
        }
        #pragma unroll
        for (int nf = 0; nf < 2; nf++) {
            int col = jt * 128 + wn + nf * 8 + 2 * cq;
            *(float2*)&Ss[(wm + r) * FUS_STRIDE + col] =
                make_float2(acc[nf][0], acc[nf][1]);
            *(float2*)&Ss[(wm + r + 8) * FUS_STRIDE + col] =
                make_float2(acc[nf][2], acc[nf][3]);
        }
        __syncthreads();
    }

    // Softmax: warp w owns rows 2w..2w+1.
    float* attn = use_ext ? attn_ext : g_attn;
    #pragma unroll
    for (int rl = 0; rl < 2; rl++) {
        int row = wid * 2 + rl;
        size_t mbase = (size_t)b * SS * SS + (size_t)(i0 + row) * SS;
        float mx = -3.4e38f;
        #pragma unroll
        for (int it = 0; it < 8; it++) {
            int c0 = (it * 32 + lane) * 4;
            float4 s4 = *(float4*)&Ss[row * FUS_STRIDE + c0];
            uchar4 u = *(const uchar4*)(g_mask8 + mbase + c0);
            s4.x = u.x ? -1e9f : s4.x * 0.125f;
            s4.y = u.y ? -1e9f : s4.y * 0.125f;
            s4.z = u.z ? -1e9f : s4.z * 0.125f;
            s4.w = u.w ? -1e9f : s4.w * 0.125f;
            *(float4*)&Ss[row * FUS_STRIDE + c0] = s4;
            mx = fmaxf(mx, fmaxf(fmaxf(s4.x, s4.y), fmaxf(s4.z, s4.w)));
        }
        #pragma unroll
        for (int o = 16; o; o >>= 1) mx = fmaxf(mx, __shfl_xor_sync(0xffffffffu, mx, o));
        float M = __shfl_sync(0xffffffffu, mx, 0);

        float s = 0.f;
        #pragma unroll
        for (int it = 0; it < 8; it++) {
            int c0 = (it * 32 + lane) * 4;
            float4 v = *(float4*)&Ss[row * FUS_STRIDE + c0];
            v.x = __expf(v.x - M); v.y = __expf(v.y - M);
            v.z = __expf(v.z - M); v.w = __expf(v.w - M);
            *(float4*)&Ss[row * FUS_STRIDE + c0] = v;
            s += v.x + v.y + v.z + v.w;
        }
        #pragma unroll
        for (int o = 16; o; o >>= 1) s += __shfl_xor_sync(0xffffffffu, s, o);
        float inv = 1.0f / s;

        size_t abase = (size_t)bh * SS * SS + (size_t)(i0 + row) * SS;
        #pragma unroll
        for (int it = 0; it < 8; it++) {
            int c0 = (it * 32 + lane) * 4;
            float4 v = *(float4*)&Ss[row * FUS_STRIDE + c0];
            *(float4*)&attn[abase + c0] =
                make_float4(f2tf(v.x * inv), f2tf(v.y * inv),
                            f2tf(v.z * inv), f2tf(v.w * inv));
        }
    }
}

// ---------------------------------------------------------------------------
// 3) Context (NN): per bh M=1024, N=64, K=1024. Grid (1, 4, 64). 2 CTAs/SM.
// ---------------------------------------------------------------------------
__global__ __launch_bounds__(256, 2) void context_kernel(const float* __restrict__ attn_ext, int use_ext) {
    extern __shared__ float sm[];
    const int bh = blockIdx.z, b = bh >> 4, h = bh & 15;
    const int bi = blockIdx.y * 256;
    const float* attn = use_ext ? attn_ext : g_attn;
    const float* ab = attn + (size_t)bh * SS * SS + (size_t)bi * SS;
    const float* vb = g_v + (size_t)b * SS * DM + h * DH;
    float acc[4][4][4] = {};
    gemm_pipe<256, 4, 4, 4, 72>(ab, SS, vb, DM, SS, sm, acc);

    const int lane = threadIdx.x & 31, wid = threadIdx.x >> 5;
    const int wm = (wid & 3) * 64, wn = (wid >> 2) * 32;
    const int r = lane >> 2, cq = lane & 3;
    float* cb = g_ctx + (size_t)b * SS * DM + h * DH;
    #pragma unroll
    for (int mf = 0; mf < 4; mf++) {
        #pragma unroll
        for (int nf = 0; nf < 4; nf++) {
            int row = bi + wm + mf * 16 + r;
            int col = wn + nf * 8 + 2 * cq;
            *(float2*)&cb[(size_t)row * DM + col] =
                make_float2(f2tf(acc[mf][nf][0]), f2tf(acc[mf][nf][1]));
            *(float2*)&cb[(size_t)(row + 8) * DM + col] =
                make_float2(f2tf(acc[mf][nf][2]), f2tf(acc[mf][nf][3]));
        }
    }
}

// ---------------------------------------------------------------------------
// 4) Output projection + residual (NN). Grid (8, 32), 128 thr, 2 CTAs/SM.
// ---------------------------------------------------------------------------
__global__ __launch_bounds__(128, 2) void outproj_kernel(
    const float* __restrict__ bo, const float* __restrict__ Qres)
{
    extern __shared__ float sm[];
    const int bm = blockIdx.y * 128, bn = blockIdx.x * 128;
    float acc[4][8][4] = {};
    gemm_pipe<128, 2, 4, 8, 136>(g_ctx + (size_t)bm * DM, DM, g_wo + bn, DM, DM, sm, acc);

    const int lane = threadIdx.x & 31, wid = threadIdx.x >> 5;
    const int wm = (wid & 1) * 64, wn = (wid >> 1) * 64;
    const int r = lane >> 2, cq = lane & 3;
    #pragma unroll
    for (int mf = 0; mf < 4; mf++) {
        #pragma unroll
        for (int nf = 0; nf < 8; nf++) {
            int row = bm + wm + mf * 16 + r;
            int col = bn + wn + nf * 8 + 2 * cq;
            float2 bia = *(const float2*)&bo[col];
            float2 q0 = *(const float2*)&Qres[(size_t)row * DM + col];
            float2 q1 = *(const float2*)&Qres[(size_t)(row + 8) * DM + col];
            *(float2*)&g_y[(size_t)row * DM + col] =
                make_float2(acc[mf][nf][0] + bia.x + q0.x, acc[mf][nf][1] + bia.y + q0.y);
            *(float2*)&g_y[(size_t)(row + 8) * DM + col] =
                make_float2(acc[mf][nf][2] + bia.x + q1.x, acc[mf][nf][3] + bia.y + q1.y);
        }
    }
}

// ---------------------------------------------------------------------------
// 5) LayerNorm over last dim (1024), biased variance, eps 1e-5. Grid 4096x256.
// ---------------------------------------------------------------------------
__global__ __launch_bounds__(256) void ln_kernel(
    const float* __restrict__ gamma, const float* __restrict__ beta,
    float* __restrict__ out)
{
    const float4* row = (const float4*)(g_y + (size_t)blockIdx.x * DM);
    const int t = threadIdx.x, lane = t & 31, w = t >> 5;
    __shared__ float s1[8], s2[8];
    float4 x = row[t];
    float a = x.x + x.y + x.z + x.w;
    float b = x.x * x.x + x.y * x.y + x.z * x.z + x.w * x.w;
    #pragma unroll
    for (int o = 16; o > 0; o >>= 1) {
        a += __shfl_xor_sync(0xffffffffu, a, o);
        b += __shfl_xor_sync(0xffffffffu, b, o);
    }
    if (lane == 0) { s1[w] = a; s2[w] = b; }
    __syncthreads();
    float A = 0.f, B2 = 0.f;
    #pragma unroll
    for (int i = 0; i < 8; i++) { A += s1[i]; B2 += s2[i]; }
    float mean = A * (1.0f / 1024.0f);
    float var = B2 * (1.0f / 1024.0f) - mean * mean;
    float rstd = rsqrtf(var + 1e-5f);
    float4 g = ((const float4*)gamma)[t];
    float4 be = ((const float4*)beta)[t];
    float4 o4;
    o4.x = (x.x - mean) * rstd * g.x + be.x;
    o4.y = (x.y - mean) * rstd * g.y + be.y;
    o4.z = (x.z - mean) * rstd * g.z + be.z;
    o4.w = (x.w - mean) * rstd * g.w + be.w;
    ((float4*)(out + (size_t)blockIdx.x * DM))[t] = o4;
}

// ---------------------------------------------------------------------------
extern "C" void kernel_launch(void* const* d_in, const int* in_sizes, int n_in,
                              void* d_out, int out_size) {
    const float* Qin   = (const float*)d_in[0];
    const void*  mask  = d_in[3];
    const float* Wq    = (const float*)d_in[4];
    const float* bq    = (const float*)d_in[5];
    const float* Wk    = (const float*)d_in[6];
    const float* bk    = (const float*)d_in[7];
    const float* Wv    = (const float*)d_in[8];
    const float* bv    = (const float*)d_in[9];
    const float* Wo    = (const float*)d_in[10];
    const float* bo    = (const float*)d_in[11];
    const float* gamma = (const float*)d_in[12];
    const float* beta  = (const float*)d_in[13];
    float* out = (float*)d_out;

    const int use_ext = (out_size > OUT_ELEMS) ? 1 : 0;
    float* attn_ext = out + OUT_ELEMS;

    cudaFuncSetAttribute(qkv_gemm, cudaFuncAttributeMaxDynamicSharedMemorySize, QKV_SMEM_BYTES);
    cudaFuncSetAttribute(outproj_kernel, cudaFuncAttributeMaxDynamicSharedMemorySize, QKV_SMEM_BYTES);
    cudaFuncSetAttribute(scores_softmax_kernel, cudaFuncAttributeMaxDynamicSharedMemorySize, FUS_SMEM_BYTES);
    cudaFuncSetAttribute(context_kernel, cudaFuncAttributeMaxDynamicSharedMemorySize, CTX_SMEM_BYTES);

    detect_mask_kernel<<<1, 32>>>((const unsigned*)mask);
    prep_kernel<<<dim3(20480), 256>>>(
        Qin, (const float*)d_in[1], (const float*)d_in[2],
        Wq, Wk, Wv, Wo, mask);
    qkv_gemm<<<dim3(8, 32, 3), 128, QKV_SMEM_BYTES>>>(bq, bk, bv);
    scores_softmax_kernel<<<dim3(32, 64), 512, FUS_SMEM_BYTES>>>(attn_ext, use_ext);
    context_kernel<<<dim3(1, 4, 64), 256, CTX_SMEM_BYTES>>>(attn_ext, use_ext);
    outproj_kernel<<<dim3(8, 32), 128, QKV_SMEM_BYTES>>>(bo, Qin);
    ln_kernel<<<dim3(MROWS), 256>>>(gamma, beta, out);
    (void)in_sizes; (void)n_in;
}